// round 2
// baseline (speedup 1.0000x reference)
#include <cuda_runtime.h>
#include <math.h>

#define M_DIM 4
#define N_DIM 64
#define B_DIM 256
#define C_DIM 512
#define H_DIM 64
#define BCH   32                 // b-rows per block
#define NB    (B_DIM / BCH)      // 8 b-chunks

// eta[n][k] produced by the tiny MLP (kernel A), consumed by kernel B.
__device__ float g_eta[N_DIM * 4];

// ETA_FAULT table (12 rows x 4), row-major.
__device__ const float g_fault[48] = {
     0.99997f, -1.0f,      0.0f,      9.1182e-18f,
    -0.55856f, -1.0f,      0.0f,     -3.7472e-10f,
   -16.919f,   14.562f,    0.086479f, 82.578f,
     1.0f,     -1.0f,      0.0f,      4.4982e-16f,
     1.6839f,  -2.2404f,  -2.5173f,   1.1147f,
    -0.55856f, -1.0f,      0.0f,     -3.7472e-10f,
     0.99997f, -1.0f,      0.0f,      9.1182e-18f,
     0.23198f, -0.78334f, -0.41194f,  3.4699f,
     1.0f,     -1.0f,      0.0f,      4.4982e-16f,
     0.99997f, -1.0f,      0.0f,      9.1182e-18f,
    -0.24548f, -0.02379f,  0.81499f,  1.5337f,
    -1.0f,     -1.0f,      0.0f,      4.407e-16f
};

// ---------------------------------------------------------------------------
// Kernel A: tiny MLP. One block, 64 threads (one per n). Precise math.
// ---------------------------------------------------------------------------
__global__ void eta_kernel(const float* __restrict__ rt_,
                           const float* __restrict__ noise,
                           const float* __restrict__ X_max,
                           const float* __restrict__ X_min,
                           const float* __restrict__ Y_max,
                           const float* __restrict__ Y_min,
                           const float* __restrict__ W1,
                           const float* __restrict__ b1,
                           const float* __restrict__ W2,
                           const float* __restrict__ b2)
{
    int n = threadIdx.x;
    if (n >= N_DIM) return;

    float rtv[9];
    #pragma unroll
    for (int i = 0; i < 9; i++) {
        float rtn = (i < 6) ? (1.0f / (1.0f + expf(-rt_[i]))) : 0.0f;
        float RT  = rtn * (X_max[i] - X_min[i]) + X_min[i];
        float nf  = (noise[n * 9 + i] * 2.0f - 1.0f) * 0.1f + 1.0f;
        rtv[i] = RT * nf;
    }

    float ext[9];
    ext[0] = rtv[0]; ext[1] = rtv[1]; ext[2] = rtv[2];
    ext[3] = rtv[3]; ext[4] = rtv[4]; ext[5] = rtv[5];
    ext[6] = rtv[1] / rtv[0];
    ext[7] = rtv[3] / rtv[2];
    ext[8] = rtv[5] / rtv[4];

    float xn[9];
    #pragma unroll
    for (int i = 0; i < 9; i++)
        xn[i] = (ext[i] - X_min[i]) / (X_max[i] - X_min[i]);

    float acc0 = b2[0], acc1 = b2[1], acc2 = b2[2], acc3 = b2[3];
    for (int j = 0; j < H_DIM; j++) {
        float h = b1[j];
        #pragma unroll
        for (int i = 0; i < 9; i++)
            h += xn[i] * W1[i * H_DIM + j];
        h = fmaxf(h, 0.0f);
        acc0 += h * W2[j * 4 + 0];
        acc1 += h * W2[j * 4 + 1];
        acc2 += h * W2[j * 4 + 2];
        acc3 += h * W2[j * 4 + 3];
    }

    g_eta[n * 4 + 0] = (1.0f / (1.0f + expf(-acc0))) * (Y_max[0] - Y_min[0]) + Y_min[0];
    g_eta[n * 4 + 1] = (1.0f / (1.0f + expf(-acc1))) * (Y_max[1] - Y_min[1]) + Y_min[1];
    g_eta[n * 4 + 2] = (1.0f / (1.0f + expf(-acc2))) * (Y_max[2] - Y_min[2]) + Y_min[2];
    g_eta[n * 4 + 3] = (1.0f / (1.0f + expf(-acc3))) * (Y_max[3] - Y_min[3]) + Y_min[3];
}

// ---------------------------------------------------------------------------
// Kernel B: fused select + tanh, HBM-bound streaming.
// Grid (NB, N, M), 128 threads. Thread t owns c = 4t..4t+3 (float4).
// out = e0 + e1*tanh((z-e2)*e3)
//     = (e0+e1) + (-2*e1) * rcp(exp(2*e3*z - 2*e2*e3) + 1)
// ---------------------------------------------------------------------------
__global__ void __launch_bounds__(128)
tanh_kernel(const float* __restrict__ z,
            const int*   __restrict__ mask,
            float*       __restrict__ out)
{
    const int m  = blockIdx.z;
    const int n  = blockIdx.y;
    const int bc = blockIdx.x;
    const int t  = threadIdx.x;

    // Shared table: rows 0..11 = fault rows, row 12 = eta[n] (this block's n).
    __shared__ float tab[13 * 4];
    if (t < 48)      tab[t]      = g_fault[t];
    else if (t < 52) tab[t]      = g_eta[n * 4 + (t - 48)];
    __syncthreads();

    const int c0 = t * 4;
    const int4 mk4 = *reinterpret_cast<const int4*>(mask + m * C_DIM + c0);
    const int mks[4] = { mk4.x, mk4.y, mk4.z, mk4.w };

    float aa[4], bb[4], s0[4], s1[4];
    #pragma unroll
    for (int j = 0; j < 4; j++) {
        int sel = (mks[j] == 0) ? 12 : (mks[j] - 1);
        float e0 = tab[sel * 4 + 0];
        float e1 = tab[sel * 4 + 1];
        float e2 = tab[sel * 4 + 2];
        float e3 = tab[sel * 4 + 3];
        aa[j] =  2.0f * e3;
        bb[j] = -2.0f * e2 * e3;
        s0[j] =  e0 + e1;
        s1[j] = -2.0f * e1;
    }

    size_t base = (((size_t)(m * N_DIM + n)) * B_DIM + (size_t)bc * BCH) * C_DIM + c0;

    #pragma unroll 2
    for (int b = 0; b < BCH; b++) {
        float4 zv = *reinterpret_cast<const float4*>(z + base);
        float zz[4] = { zv.x, zv.y, zv.z, zv.w };
        float o[4];
        #pragma unroll
        for (int j = 0; j < 4; j++) {
            float arg = fmaf(zz[j], aa[j], bb[j]);   // 2*e3*(z - e2)
            float u   = __expf(arg);                  // MUFU ex2
            o[j] = s0[j] + __fdividef(s1[j], u + 1.0f);  // MUFU rcp
        }
        *reinterpret_cast<float4*>(out + base) = make_float4(o[0], o[1], o[2], o[3]);
        base += C_DIM;
    }
}

// ---------------------------------------------------------------------------
// Launch. Input order per metadata: z, rt_, noise, X_max, X_min, Y_max, Y_min,
// W1, b1, W2, b2, mask. Output: float32, same shape as z.
// ---------------------------------------------------------------------------
extern "C" void kernel_launch(void* const* d_in, const int* in_sizes, int n_in,
                              void* d_out, int out_size)
{
    const float* z     = (const float*)d_in[0];
    const float* rt_   = (const float*)d_in[1];
    const float* noise = (const float*)d_in[2];
    const float* X_max = (const float*)d_in[3];
    const float* X_min = (const float*)d_in[4];
    const float* Y_max = (const float*)d_in[5];
    const float* Y_min = (const float*)d_in[6];
    const float* W1    = (const float*)d_in[7];
    const float* b1    = (const float*)d_in[8];
    const float* W2    = (const float*)d_in[9];
    const float* b2    = (const float*)d_in[10];
    const int*   mask  = (const int*)d_in[11];
    float* out = (float*)d_out;

    eta_kernel<<<1, 64>>>(rt_, noise, X_max, X_min, Y_max, Y_min, W1, b1, W2, b2);

    dim3 grid(NB, N_DIM, M_DIM);
    tanh_kernel<<<grid, 128>>>(z, mask, out);
}

// round 13
// speedup vs baseline: 1.2824x; 1.2824x over previous
#include <cuda_runtime.h>
#include <math.h>

#define M_DIM 4
#define N_DIM 64
#define B_DIM 256
#define C_DIM 512
#define H_DIM 64
#define BCH   32                 // b-rows per block
#define NB    (B_DIM / BCH)      // 8 b-chunks

// ETA_FAULT table (12 rows x 4), row-major.
__device__ const float g_fault[48] = {
     0.99997f, -1.0f,      0.0f,      9.1182e-18f,
    -0.55856f, -1.0f,      0.0f,     -3.7472e-10f,
   -16.919f,   14.562f,    0.086479f, 82.578f,
     1.0f,     -1.0f,      0.0f,      4.4982e-16f,
     1.6839f,  -2.2404f,  -2.5173f,   1.1147f,
    -0.55856f, -1.0f,      0.0f,     -3.7472e-10f,
     0.99997f, -1.0f,      0.0f,      9.1182e-18f,
     0.23198f, -0.78334f, -0.41194f,  3.4699f,
     1.0f,     -1.0f,      0.0f,      4.4982e-16f,
     0.99997f, -1.0f,      0.0f,      9.1182e-18f,
    -0.24548f, -0.02379f,  0.81499f,  1.5337f,
    -1.0f,     -1.0f,      0.0f,      4.407e-16f
};

// ---------------------------------------------------------------------------
// Fused kernel: per-block eta[n] MLP (parallel over hidden units) + streaming
// select/tanh. Grid (NB, N, M), 256 threads.
// out = e0 + e1*tanh((z-e2)*e3)
//     = (e0+e1) + (-2*e1) * rcp(exp(2*e3*z - 2*e2*e3) + 1)
// ---------------------------------------------------------------------------
__global__ void __launch_bounds__(256)
fused_kernel(const float* __restrict__ z,
             const float* __restrict__ rt_,
             const float* __restrict__ noise,
             const float* __restrict__ X_max,
             const float* __restrict__ X_min,
             const float* __restrict__ Y_max,
             const float* __restrict__ Y_min,
             const float* __restrict__ W1,
             const float* __restrict__ b1,
             const float* __restrict__ W2,
             const float* __restrict__ b2,
             const int*   __restrict__ mask,
             float*       __restrict__ out)
{
    const int m  = blockIdx.z;
    const int n  = blockIdx.y;
    const int bc = blockIdx.x;
    const int t  = threadIdx.x;

    // Shared: rows 0..11 = fault rows, row 12 = eta[n]; red = MLP reduction.
    __shared__ float tab[13 * 4];
    __shared__ float red[H_DIM][4];

    if (t < 48) tab[t] = g_fault[t];

    // ---- eta[n] MLP, parallel over the 64 hidden neurons ----
    if (t < H_DIM) {
        float rtv[9];
        #pragma unroll
        for (int i = 0; i < 9; i++) {
            float xmin = X_min[i], xmax = X_max[i];
            float rtn = (i < 6) ? (1.0f / (1.0f + expf(-rt_[i]))) : 0.0f;
            float RT  = rtn * (xmax - xmin) + xmin;
            float nf  = (noise[n * 9 + i] * 2.0f - 1.0f) * 0.1f + 1.0f;
            rtv[i] = RT * nf;
        }
        float ext[9];
        ext[0] = rtv[0]; ext[1] = rtv[1]; ext[2] = rtv[2];
        ext[3] = rtv[3]; ext[4] = rtv[4]; ext[5] = rtv[5];
        ext[6] = rtv[1] / rtv[0];
        ext[7] = rtv[3] / rtv[2];
        ext[8] = rtv[5] / rtv[4];

        float h = b1[t];
        #pragma unroll
        for (int i = 0; i < 9; i++) {
            float xn = (ext[i] - X_min[i]) / (X_max[i] - X_min[i]);
            h = fmaf(xn, W1[i * H_DIM + t], h);
        }
        h = fmaxf(h, 0.0f);
        red[t][0] = h * W2[t * 4 + 0];
        red[t][1] = h * W2[t * 4 + 1];
        red[t][2] = h * W2[t * 4 + 2];
        red[t][3] = h * W2[t * 4 + 3];
    }
    __syncthreads();

    if (t < 4) {
        float s = b2[t];
        #pragma unroll
        for (int j = 0; j < H_DIM; j++) s += red[j][t];
        float sg = 1.0f / (1.0f + expf(-s));
        tab[48 + t] = sg * (Y_max[t] - Y_min[t]) + Y_min[t];
    }
    __syncthreads();

    // ---- per-thread column params ----
    const int c4    = t & 127;          // which float4 column (0..127)
    const int rhalf = t >> 7;           // row parity within a 2-row step
    const int c0    = c4 * 4;

    const int4 mk4 = *reinterpret_cast<const int4*>(mask + m * C_DIM + c0);
    const int mks[4] = { mk4.x, mk4.y, mk4.z, mk4.w };

    float aa[4], bb[4], s0[4], s1[4];
    #pragma unroll
    for (int j = 0; j < 4; j++) {
        int sel = (mks[j] == 0) ? 12 : (mks[j] - 1);
        float e0 = tab[sel * 4 + 0];
        float e1 = tab[sel * 4 + 1];
        float e2 = tab[sel * 4 + 2];
        float e3 = tab[sel * 4 + 3];
        aa[j] =  2.0f * e3;
        bb[j] = -2.0f * e2 * e3;
        s0[j] =  e0 + e1;
        s1[j] = -2.0f * e1;
    }

    // ---- streaming loop: 32 rows, 2 rows per step, 4 steps batched ----
    size_t base = (((size_t)(m * N_DIM + n)) * B_DIM + (size_t)bc * BCH + rhalf) * C_DIM + c0;
    const size_t step = 2 * C_DIM;

    #pragma unroll 1
    for (int ob = 0; ob < 4; ob++) {
        float4 zv[4];
        #pragma unroll
        for (int u = 0; u < 4; u++)
            zv[u] = *reinterpret_cast<const float4*>(z + base + (size_t)u * step);

        #pragma unroll
        for (int u = 0; u < 4; u++) {
            float zz[4] = { zv[u].x, zv[u].y, zv[u].z, zv[u].w };
            float o[4];
            #pragma unroll
            for (int j = 0; j < 4; j++) {
                float arg = fmaf(zz[j], aa[j], bb[j]);       // 2*e3*(z - e2)
                float uu  = __expf(arg);                     // MUFU ex2
                o[j] = s0[j] + __fdividef(s1[j], uu + 1.0f); // MUFU rcp
            }
            *reinterpret_cast<float4*>(out + base + (size_t)u * step) =
                make_float4(o[0], o[1], o[2], o[3]);
        }
        base += 4 * step;
    }
}

// ---------------------------------------------------------------------------
// Launch. Input order per metadata: z, rt_, noise, X_max, X_min, Y_max, Y_min,
// W1, b1, W2, b2, mask. Output: float32, same shape as z.
// ---------------------------------------------------------------------------
extern "C" void kernel_launch(void* const* d_in, const int* in_sizes, int n_in,
                              void* d_out, int out_size)
{
    const float* z     = (const float*)d_in[0];
    const float* rt_   = (const float*)d_in[1];
    const float* noise = (const float*)d_in[2];
    const float* X_max = (const float*)d_in[3];
    const float* X_min = (const float*)d_in[4];
    const float* Y_max = (const float*)d_in[5];
    const float* Y_min = (const float*)d_in[6];
    const float* W1    = (const float*)d_in[7];
    const float* b1    = (const float*)d_in[8];
    const float* W2    = (const float*)d_in[9];
    const float* b2    = (const float*)d_in[10];
    const int*   mask  = (const int*)d_in[11];
    float* out = (float*)d_out;

    dim3 grid(NB, N_DIM, M_DIM);
    fused_kernel<<<grid, 256>>>(z, rt_, noise, X_max, X_min, Y_max, Y_min,
                                W1, b1, W2, b2, mask, out);
}

// round 17
// speedup vs baseline: 1.3208x; 1.0300x over previous
#include <cuda_runtime.h>
#include <math.h>

#define M_DIM 4
#define N_DIM 64
#define B_DIM 256
#define C_DIM 512
#define H_DIM 64
#define BCH   32                 // b-rows per block
#define NB    (B_DIM / BCH)      // 8 b-chunks

// ETA_FAULT table (12 rows x 4), row-major.
__device__ const float g_fault[48] = {
     0.99997f, -1.0f,      0.0f,      9.1182e-18f,
    -0.55856f, -1.0f,      0.0f,     -3.7472e-10f,
   -16.919f,   14.562f,    0.086479f, 82.578f,
     1.0f,     -1.0f,      0.0f,      4.4982e-16f,
     1.6839f,  -2.2404f,  -2.5173f,   1.1147f,
    -0.55856f, -1.0f,      0.0f,     -3.7472e-10f,
     0.99997f, -1.0f,      0.0f,      9.1182e-18f,
     0.23198f, -0.78334f, -0.41194f,  3.4699f,
     1.0f,     -1.0f,      0.0f,      4.4982e-16f,
     0.99997f, -1.0f,      0.0f,      9.1182e-18f,
    -0.24548f, -0.02379f,  0.81499f,  1.5337f,
    -1.0f,     -1.0f,      0.0f,      4.407e-16f
};

// ---------------------------------------------------------------------------
// Fused kernel: per-block eta[n] MLP prologue + streaming select/tanh.
// Grid (NB, N, M), 256 threads. 2 outer iterations x 8-deep batched float4.
// out = e0 + e1*tanh((z-e2)*e3)
//     = (e0+e1) + (-2*e1) * rcp(exp(2*e3*z - 2*e2*e3) + 1)
// ---------------------------------------------------------------------------
__global__ void __launch_bounds__(256)
fused_kernel(const float* __restrict__ z,
             const float* __restrict__ rt_,
             const float* __restrict__ noise,
             const float* __restrict__ X_max,
             const float* __restrict__ X_min,
             const float* __restrict__ Y_max,
             const float* __restrict__ Y_min,
             const float* __restrict__ W1,
             const float* __restrict__ b1,
             const float* __restrict__ W2,
             const float* __restrict__ b2,
             const int*   __restrict__ mask,
             float*       __restrict__ out)
{
    const int m  = blockIdx.z;
    const int n  = blockIdx.y;
    const int bc = blockIdx.x;
    const int t  = threadIdx.x;

    // Shared: rows 0..11 = fault rows, row 12 = eta[n]; red = MLP reduction.
    __shared__ float tab[13 * 4];
    __shared__ float red[H_DIM][4];

    if (t < 48) tab[t] = g_fault[t];

    // ---- eta[n] MLP, parallel over the 64 hidden neurons ----
    if (t < H_DIM) {
        float rtv[9];
        #pragma unroll
        for (int i = 0; i < 9; i++) {
            float xmin = X_min[i], xmax = X_max[i];
            float rtn = (i < 6) ? (1.0f / (1.0f + expf(-rt_[i]))) : 0.0f;
            float RT  = rtn * (xmax - xmin) + xmin;
            float nf  = (noise[n * 9 + i] * 2.0f - 1.0f) * 0.1f + 1.0f;
            rtv[i] = RT * nf;
        }
        float ext[9];
        ext[0] = rtv[0]; ext[1] = rtv[1]; ext[2] = rtv[2];
        ext[3] = rtv[3]; ext[4] = rtv[4]; ext[5] = rtv[5];
        ext[6] = rtv[1] / rtv[0];
        ext[7] = rtv[3] / rtv[2];
        ext[8] = rtv[5] / rtv[4];

        float h = b1[t];
        #pragma unroll
        for (int i = 0; i < 9; i++) {
            float xn = (ext[i] - X_min[i]) / (X_max[i] - X_min[i]);
            h = fmaf(xn, W1[i * H_DIM + t], h);
        }
        h = fmaxf(h, 0.0f);
        red[t][0] = h * W2[t * 4 + 0];
        red[t][1] = h * W2[t * 4 + 1];
        red[t][2] = h * W2[t * 4 + 2];
        red[t][3] = h * W2[t * 4 + 3];
    }
    __syncthreads();

    if (t < 4) {
        float s = b2[t];
        #pragma unroll
        for (int j = 0; j < H_DIM; j++) s += red[j][t];
        float sg = 1.0f / (1.0f + expf(-s));
        tab[48 + t] = sg * (Y_max[t] - Y_min[t]) + Y_min[t];
    }
    __syncthreads();

    // ---- per-thread column params ----
    const int c4    = t & 127;          // which float4 column (0..127)
    const int rhalf = t >> 7;           // row parity within a 2-row step
    const int c0    = c4 * 4;

    const int4 mk4 = *reinterpret_cast<const int4*>(mask + m * C_DIM + c0);
    const int mks[4] = { mk4.x, mk4.y, mk4.z, mk4.w };

    float aa[4], bb[4], s0[4], s1[4];
    #pragma unroll
    for (int j = 0; j < 4; j++) {
        int sel = (mks[j] == 0) ? 12 : (mks[j] - 1);
        float e0 = tab[sel * 4 + 0];
        float e1 = tab[sel * 4 + 1];
        float e2 = tab[sel * 4 + 2];
        float e3 = tab[sel * 4 + 3];
        aa[j] =  2.0f * e3;
        bb[j] = -2.0f * e2 * e3;
        s0[j] =  e0 + e1;
        s1[j] = -2.0f * e1;
    }

    // ---- streaming loop: 32 rows, 2 rows per step (parity), 8-deep batch ----
    size_t base = (((size_t)(m * N_DIM + n)) * B_DIM + (size_t)bc * BCH + rhalf) * C_DIM + c0;
    const size_t step = 2 * C_DIM;

    #pragma unroll 1
    for (int ob = 0; ob < 2; ob++) {
        float4 zv[8];
        #pragma unroll
        for (int u = 0; u < 8; u++)
            zv[u] = __ldcs(reinterpret_cast<const float4*>(z + base + (size_t)u * step));

        #pragma unroll
        for (int u = 0; u < 8; u++) {
            float zz[4] = { zv[u].x, zv[u].y, zv[u].z, zv[u].w };
            float o[4];
            #pragma unroll
            for (int j = 0; j < 4; j++) {
                float arg = fmaf(zz[j], aa[j], bb[j]);       // 2*e3*(z - e2)
                float uu  = __expf(arg);                     // MUFU ex2
                o[j] = s0[j] + __fdividef(s1[j], uu + 1.0f); // MUFU rcp
            }
            __stcs(reinterpret_cast<float4*>(out + base + (size_t)u * step),
                   make_float4(o[0], o[1], o[2], o[3]));
        }
        base += 8 * step;
    }
}

// ---------------------------------------------------------------------------
// Launch. Input order per metadata: z, rt_, noise, X_max, X_min, Y_max, Y_min,
// W1, b1, W2, b2, mask. Output: float32, same shape as z.
// ---------------------------------------------------------------------------
extern "C" void kernel_launch(void* const* d_in, const int* in_sizes, int n_in,
                              void* d_out, int out_size)
{
    const float* z     = (const float*)d_in[0];
    const float* rt_   = (const float*)d_in[1];
    const float* noise = (const float*)d_in[2];
    const float* X_max = (const float*)d_in[3];
    const float* X_min = (const float*)d_in[4];
    const float* Y_max = (const float*)d_in[5];
    const float* Y_min = (const float*)d_in[6];
    const float* W1    = (const float*)d_in[7];
    const float* b1    = (const float*)d_in[8];
    const float* W2    = (const float*)d_in[9];
    const float* b2    = (const float*)d_in[10];
    const int*   mask  = (const int*)d_in[11];
    float* out = (float*)d_out;

    dim3 grid(NB, N_DIM, M_DIM);
    fused_kernel<<<grid, 256>>>(z, rt_, noise, X_max, X_min, Y_max, Y_min,
                                W1, b1, W2, b2, mask, out);
}